// round 5
// baseline (speedup 1.0000x reference)
#include <cuda_runtime.h>
#include <cuda_bf16.h>
#include <cstdint>

#define PITCH 1026
// g_pos[n][i][t + s(i)], s(i)=(i+1)&1 -> flash shifted reads are 8B aligned
__device__ float g_pos[(size_t)64 * 1024 * PITCH];

// ------------------------------ helpers -----------------------------------
__device__ __forceinline__ uint32_t smem_u32(const void* p) {
    uint32_t a;
    asm("{ .reg .u64 t; cvta.to.shared.u64 t, %1; cvt.u32.u64 %0, t; }" : "=r"(a) : "l"(p));
    return a;
}
__device__ __forceinline__ void ldsm4(uint32_t* r, uint32_t a) {
    asm volatile("ldmatrix.sync.aligned.m8n8.x4.shared.b16 {%0,%1,%2,%3}, [%4];"
        : "=r"(r[0]), "=r"(r[1]), "=r"(r[2]), "=r"(r[3]) : "r"(a));
}
__device__ __forceinline__ void ldsm2(uint32_t* r, uint32_t a) {
    asm volatile("ldmatrix.sync.aligned.m8n8.x2.shared.b16 {%0,%1}, [%2];"
        : "=r"(r[0]), "=r"(r[1]) : "r"(a));
}
__device__ __forceinline__ void mma16816(float* c, const uint32_t* a, const uint32_t* b) {
    asm volatile("mma.sync.aligned.m16n8k16.row.col.f32.bf16.bf16.f32 "
        "{%0,%1,%2,%3}, {%4,%5,%6,%7}, {%8,%9}, {%0,%1,%2,%3};"
        : "+f"(c[0]), "+f"(c[1]), "+f"(c[2]), "+f"(c[3])
        : "r"(a[0]), "r"(a[1]), "r"(a[2]), "r"(a[3]), "r"(b[0]), "r"(b[1]));
}
__device__ __forceinline__ void splitpair(float a, float b, uint32_t& hi, uint32_t& lo) {
    __nv_bfloat16 ah = __float2bfloat16_rn(a), bh = __float2bfloat16_rn(b);
    __nv_bfloat16 al = __float2bfloat16_rn(a - __bfloat162float(ah));
    __nv_bfloat16 bl = __float2bfloat16_rn(b - __bfloat162float(bh));
    __nv_bfloat162 h2, l2; h2.x = ah; h2.y = bh; l2.x = al; l2.y = bl;
    hi = *reinterpret_cast<uint32_t*>(&h2); lo = *reinterpret_cast<uint32_t*>(&l2);
}
__device__ __forceinline__ float posval(const float* pb, int i, int j) {
    if (j <= i)     return pb[(size_t)i * PITCH + (1023 + j - i + ((i + 1) & 1))];
    if (j == i + 1) return 0.0f;
    return pb[(size_t)(i + 1) * PITCH + (j - i - 2 + ((i + 2) & 1))];
}
__device__ __forceinline__ float2 pos2(const float* pb, int i, int j) {
    if (j + 1 <= i)
        return *(const float2*)(pb + (size_t)i * PITCH + (1023 - i + ((i + 1) & 1)) + j);
    if (j >= i + 2)
        return *(const float2*)(pb + (size_t)(i + 1) * PITCH + (((i + 2) & 1) - i - 2) + j);
    float2 r;
    r.x = posval(pb, i, j);
    r.y = posval(pb, i, j + 1);
    return r;
}

// A-tile / K-tile smem: 128 rows x 72 bf16 (144 B pitch; 8 rows mod 128B = distinct -> ldmatrix conflict-free)
// P / V^T smem: rows x 136 bf16 (272 B pitch; same property)

// ---------------------------------------------------------------------------
// Kernel 1: g_pos(shifted) = (q*0.125 + vbias) . R^T  via mma.sync bf16x3.
// grid (8 t, 8 i, 64 n), 256 threads = 8 warps in 2(M)x4(N).
// ---------------------------------------------------------------------------
#define POS_SMEM 73728
__global__ __launch_bounds__(256)
void pos_mma(const float* __restrict__ q, const float* __restrict__ vbias,
             const float* __restrict__ R)
{
    extern __shared__ char cb[];
    uint32_t sb = smem_u32(cb);
    const uint32_t QH = 0, QL = 18432, RH = 36864, RL = 55296;

    const int tid = threadIdx.x, lane = tid & 31, wid = tid >> 5;
    const int wm = wid >> 2, wn = wid & 3;
    const int n = blockIdx.z, h = n & 15;
    const int i0 = blockIdx.y << 7, t0 = blockIdx.x << 7;

    const float* qb = q + (size_t)n * 65536 + (size_t)i0 * 64;
    const float* rb = R + (size_t)h * (2048 * 64) + (size_t)t0 * 64;

    #pragma unroll
    for (int it = 0; it < 8; ++it) {
        int fi = it * 256 + tid;
        int r = fi >> 4, d = (fi & 15) << 2;
        float4 f = *(const float4*)(qb + r * 64 + d);
        float4 bs = *(const float4*)(vbias + h * 64 + d);
        f.x = f.x * 0.125f + bs.x; f.y = f.y * 0.125f + bs.y;
        f.z = f.z * 0.125f + bs.z; f.w = f.w * 0.125f + bs.w;
        uint2 H, L;
        splitpair(f.x, f.y, H.x, L.x); splitpair(f.z, f.w, H.y, L.y);
        *(uint2*)(cb + QH + r * 144 + d * 2) = H;
        *(uint2*)(cb + QL + r * 144 + d * 2) = L;
        float4 g = *(const float4*)(rb + r * 64 + d);
        splitpair(g.x, g.y, H.x, L.x); splitpair(g.z, g.w, H.y, L.y);
        *(uint2*)(cb + RH + r * 144 + d * 2) = H;
        *(uint2*)(cb + RL + r * 144 + d * 2) = L;
    }
    __syncthreads();

    float C[4][4][4] = {};

    // pass 1+2: A-hi x (B-hi, B-lo)
    #pragma unroll
    for (int ks = 0; ks < 4; ++ks) {
        uint32_t a[4][4], bh[4][2], bl[4][2];
        #pragma unroll
        for (int mt = 0; mt < 4; ++mt)
            ldsm4(a[mt], sb + QH + (wm * 64 + mt * 16 + (lane & 15)) * 144 +
                         (ks * 16 + ((lane >> 4) << 3)) * 2);
        #pragma unroll
        for (int nt = 0; nt < 4; ++nt) {
            uint32_t ao = (wn * 32 + nt * 8 + (lane & 7)) * 144 +
                          (ks * 16 + (((lane >> 3) & 1) << 3)) * 2;
            ldsm2(bh[nt], sb + RH + ao);
            ldsm2(bl[nt], sb + RL + ao);
        }
        #pragma unroll
        for (int mt = 0; mt < 4; ++mt)
            #pragma unroll
            for (int nt = 0; nt < 4; ++nt) {
                mma16816(C[mt][nt], a[mt], bh[nt]);
                mma16816(C[mt][nt], a[mt], bl[nt]);
            }
    }
    // pass 3: A-lo x B-hi
    #pragma unroll
    for (int ks = 0; ks < 4; ++ks) {
        uint32_t a[4][4], bh[4][2];
        #pragma unroll
        for (int mt = 0; mt < 4; ++mt)
            ldsm4(a[mt], sb + QL + (wm * 64 + mt * 16 + (lane & 15)) * 144 +
                         (ks * 16 + ((lane >> 4) << 3)) * 2);
        #pragma unroll
        for (int nt = 0; nt < 4; ++nt)
            ldsm2(bh[nt], sb + RH + (wn * 32 + nt * 8 + (lane & 7)) * 144 +
                          (ks * 16 + (((lane >> 3) & 1) << 3)) * 2);
        #pragma unroll
        for (int mt = 0; mt < 4; ++mt)
            #pragma unroll
            for (int nt = 0; nt < 4; ++nt)
                mma16816(C[mt][nt], a[mt], bh[nt]);
    }

    float* gpn = g_pos + (size_t)n * (1024 * PITCH);
    #pragma unroll
    for (int mt = 0; mt < 4; ++mt) {
        const int i1 = i0 + wm * 64 + mt * 16 + (lane >> 2);
        const int i2 = i1 + 8;
        float* r1 = gpn + (size_t)i1 * PITCH + ((i1 + 1) & 1);
        float* r2 = gpn + (size_t)i2 * PITCH + ((i2 + 1) & 1);
        #pragma unroll
        for (int nt = 0; nt < 4; ++nt) {
            const int jc = t0 + wn * 32 + nt * 8 + ((lane & 3) << 1);
            r1[jc] = C[mt][nt][0]; r1[jc + 1] = C[mt][nt][1];
            r2[jc] = C[mt][nt][2]; r2[jc + 1] = C[mt][nt][3];
        }
    }
}

// ---------------------------------------------------------------------------
// Kernel 2: flash attention via mma.sync bf16x3.
// grid (8 i-tiles, 64 n), 256 threads = 8 warps 2(M)x4(N).
// S phase: warp tile 64x32 (j).  PV phase: warp tile 64(i) x 16(d), k=128.
// O accumulated fp32 in registers across all kt; softmax without max-sub.
// ---------------------------------------------------------------------------
#define QUH_O 0
#define QUL_O 18432
#define KH_O  36864
#define KL_O  55296
#define VTH_O 73728
#define VTL_O 91136
#define PH_O  108544
#define PL_O  143360
#define LS_O  178176
#define FLASH_SMEM (LS_O + 2048)

__global__ __launch_bounds__(256)
void flash_mma(const float* __restrict__ q, const float* __restrict__ k,
               const float* __restrict__ v, const float* __restrict__ ubias,
               float* __restrict__ out)
{
    extern __shared__ char cb[];
    uint32_t sb = smem_u32(cb);

    const int tid = threadIdx.x, lane = tid & 31, wid = tid >> 5;
    const int wm = wid >> 2, wn = wid & 3;
    const int n = blockIdx.y, h = n & 15;
    const int i0 = blockIdx.x << 7;

    // stage Qu = q*0.125 + u_bias (hi/lo)
    const float* qb = q + (size_t)n * 65536 + (size_t)i0 * 64;
    #pragma unroll
    for (int it = 0; it < 8; ++it) {
        int fi = it * 256 + tid;
        int r = fi >> 4, d = (fi & 15) << 2;
        float4 f = *(const float4*)(qb + r * 64 + d);
        float4 bs = *(const float4*)(ubias + h * 64 + d);
        f.x = f.x * 0.125f + bs.x; f.y = f.y * 0.125f + bs.y;
        f.z = f.z * 0.125f + bs.z; f.w = f.w * 0.125f + bs.w;
        uint2 H, L;
        splitpair(f.x, f.y, H.x, L.x); splitpair(f.z, f.w, H.y, L.y);
        *(uint2*)(cb + QUH_O + r * 144 + d * 2) = H;
        *(uint2*)(cb + QUL_O + r * 144 + d * 2) = L;
    }

    float oC[4][2][4] = {};
    float ls[8] = {};
    const float* pb  = g_pos + (size_t)n * (1024 * PITCH);
    const float* kb0 = k + (size_t)n * 65536;
    const float* vb0 = v + (size_t)n * 65536;

    for (int kt = 0; kt < 8; ++kt) {
        __syncthreads();   // prev PV done reading P/Vt/K before restage

        // ---- stage K (hi/lo, [j][72]) and V^T (hi/lo, [d][136]) ----
        const float* kb = kb0 + ((size_t)kt << 13);
        const float* vb = vb0 + ((size_t)kt << 13);
        #pragma unroll
        for (int it = 0; it < 8; ++it) {
            int fi = it * 256 + tid;
            int r = fi >> 4, d = (fi & 15) << 2;
            float4 f = *(const float4*)(kb + r * 64 + d);
            uint2 H, L;
            splitpair(f.x, f.y, H.x, L.x); splitpair(f.z, f.w, H.y, L.y);
            *(uint2*)(cb + KH_O + r * 144 + d * 2) = H;
            *(uint2*)(cb + KL_O + r * 144 + d * 2) = L;
            float4 g = *(const float4*)(vb + r * 64 + d);
            float gv[4] = {g.x, g.y, g.z, g.w};
            #pragma unroll
            for (int rr = 0; rr < 4; ++rr) {
                int dd = d + rr;
                __nv_bfloat16 hh = __float2bfloat16_rn(gv[rr]);
                __nv_bfloat16 ll = __float2bfloat16_rn(gv[rr] - __bfloat162float(hh));
                *(__nv_bfloat16*)(cb + VTH_O + dd * 272 + r * 2) = hh;
                *(__nv_bfloat16*)(cb + VTL_O + dd * 272 + r * 2) = ll;
            }
        }
        __syncthreads();

        // ---- S = Qu . K^T  (bf16x3) ----
        float sC[4][4][4] = {};
        #pragma unroll
        for (int ks = 0; ks < 4; ++ks) {
            uint32_t a[4][4], bh[4][2], bl[4][2];
            #pragma unroll
            for (int mt = 0; mt < 4; ++mt)
                ldsm4(a[mt], sb + QUH_O + (wm * 64 + mt * 16 + (lane & 15)) * 144 +
                             (ks * 16 + ((lane >> 4) << 3)) * 2);
            #pragma unroll
            for (int nt = 0; nt < 4; ++nt) {
                uint32_t ao = (wn * 32 + nt * 8 + (lane & 7)) * 144 +
                              (ks * 16 + (((lane >> 3) & 1) << 3)) * 2;
                ldsm2(bh[nt], sb + KH_O + ao);
                ldsm2(bl[nt], sb + KL_O + ao);
            }
            #pragma unroll
            for (int mt = 0; mt < 4; ++mt)
                #pragma unroll
                for (int nt = 0; nt < 4; ++nt) {
                    mma16816(sC[mt][nt], a[mt], bh[nt]);
                    mma16816(sC[mt][nt], a[mt], bl[nt]);
                }
        }
        #pragma unroll
        for (int ks = 0; ks < 4; ++ks) {
            uint32_t a[4][4], bh[4][2];
            #pragma unroll
            for (int mt = 0; mt < 4; ++mt)
                ldsm4(a[mt], sb + QUL_O + (wm * 64 + mt * 16 + (lane & 15)) * 144 +
                             (ks * 16 + ((lane >> 4) << 3)) * 2);
            #pragma unroll
            for (int nt = 0; nt < 4; ++nt)
                ldsm2(bh[nt], sb + KH_O + (wn * 32 + nt * 8 + (lane & 7)) * 144 +
                              (ks * 16 + (((lane >> 3) & 1) << 3)) * 2);
            #pragma unroll
            for (int mt = 0; mt < 4; ++mt)
                #pragma unroll
                for (int nt = 0; nt < 4; ++nt)
                    mma16816(sC[mt][nt], a[mt], bh[nt]);
        }

        // ---- add shifted pos, exp (no max-sub), split -> P smem ----
        #pragma unroll
        for (int mt = 0; mt < 4; ++mt) {
            const int ir1 = wm * 64 + mt * 16 + (lane >> 2);
            const int i1 = i0 + ir1, i2 = i1 + 8;
            #pragma unroll
            for (int nt = 0; nt < 4; ++nt) {
                const int jloc = wn * 32 + nt * 8 + ((lane & 3) << 1);
                const int j = (kt << 7) + jloc;
                float2 pp = pos2(pb, i1, j);
                float e0 = __expf(sC[mt][nt][0] + pp.x);
                float e1 = __expf(sC[mt][nt][1] + pp.y);
                ls[mt * 2] += e0 + e1;
                uint32_t H, L;
                splitpair(e0, e1, H, L);
                *(uint32_t*)(cb + PH_O + ir1 * 272 + jloc * 2) = H;
                *(uint32_t*)(cb + PL_O + ir1 * 272 + jloc * 2) = L;
                pp = pos2(pb, i2, j);
                e0 = __expf(sC[mt][nt][2] + pp.x);
                e1 = __expf(sC[mt][nt][3] + pp.y);
                ls[mt * 2 + 1] += e0 + e1;
                splitpair(e0, e1, H, L);
                *(uint32_t*)(cb + PH_O + (ir1 + 8) * 272 + jloc * 2) = H;
                *(uint32_t*)(cb + PL_O + (ir1 + 8) * 272 + jloc * 2) = L;
            }
        }
        __syncthreads();

        // ---- O += P . V  (bf16x3, fp32 reg accum) ----
        #pragma unroll
        for (int ks = 0; ks < 8; ++ks) {
            uint32_t aH[4][4], bH[2][2], bL[2][2];
            #pragma unroll
            for (int mt = 0; mt < 4; ++mt)
                ldsm4(aH[mt], sb + PH_O + (wm * 64 + mt * 16 + (lane & 15)) * 272 +
                              (ks * 16 + ((lane >> 4) << 3)) * 2);
            #pragma unroll
            for (int nt = 0; nt < 2; ++nt) {
                uint32_t ao = (wn * 16 + nt * 8 + (lane & 7)) * 272 +
                              (ks * 16 + (((lane >> 3) & 1) << 3)) * 2;
                ldsm2(bH[nt], sb + VTH_O + ao);
                ldsm2(bL[nt], sb + VTL_O + ao);
            }
            #pragma unroll
            for (int mt = 0; mt < 4; ++mt)
                #pragma unroll
                for (int nt = 0; nt < 2; ++nt) {
                    mma16816(oC[mt][nt], aH[mt], bH[nt]);
                    mma16816(oC[mt][nt], aH[mt], bL[nt]);
                }
        }
        #pragma unroll
        for (int ks = 0; ks < 8; ++ks) {
            uint32_t aL[4][4], bH[2][2];
            #pragma unroll
            for (int mt = 0; mt < 4; ++mt)
                ldsm4(aL[mt], sb + PL_O + (wm * 64 + mt * 16 + (lane & 15)) * 272 +
                              (ks * 16 + ((lane >> 4) << 3)) * 2);
            #pragma unroll
            for (int nt = 0; nt < 2; ++nt)
                ldsm2(bH[nt], sb + VTH_O + (wn * 16 + nt * 8 + (lane & 7)) * 272 +
                              (ks * 16 + (((lane >> 3) & 1) << 3)) * 2);
            #pragma unroll
            for (int mt = 0; mt < 4; ++mt)
                #pragma unroll
                for (int nt = 0; nt < 2; ++nt)
                    mma16816(oC[mt][nt], aL[mt], bH[nt]);
        }
    }

    // ---- row-sum reduction across quad + 4 N-warps ----
    float* lsm = (float*)(cb + LS_O);
    #pragma unroll
    for (int p = 0; p < 8; ++p) {
        float vv = ls[p];
        vv += __shfl_xor_sync(0xffffffffu, vv, 1);
        vv += __shfl_xor_sync(0xffffffffu, vv, 2);
        ls[p] = vv;
    }
    if ((lane & 3) == 0) {
        #pragma unroll
        for (int mt = 0; mt < 4; ++mt) {
            int ir1 = wm * 64 + mt * 16 + (lane >> 2);
            lsm[wn * 128 + ir1] = ls[mt * 2];
            lsm[wn * 128 + ir1 + 8] = ls[mt * 2 + 1];
        }
    }
    __syncthreads();

    // ---- normalize + store O ----
    #pragma unroll
    for (int mt = 0; mt < 4; ++mt) {
        const int ir1 = wm * 64 + mt * 16 + (lane >> 2);
        const int ir2 = ir1 + 8;
        float inv1 = 1.0f / (lsm[ir1] + lsm[128 + ir1] + lsm[256 + ir1] + lsm[384 + ir1]);
        float inv2 = 1.0f / (lsm[ir2] + lsm[128 + ir2] + lsm[256 + ir2] + lsm[384 + ir2]);
        #pragma unroll
        for (int nt = 0; nt < 2; ++nt) {
            const int dcol = wn * 16 + nt * 8 + ((lane & 3) << 1);
            float* o1 = out + (size_t)n * 65536 + (size_t)(i0 + ir1) * 64 + dcol;
            float* o2 = out + (size_t)n * 65536 + (size_t)(i0 + ir2) * 64 + dcol;
            o1[0] = oC[mt][nt][0] * inv1; o1[1] = oC[mt][nt][1] * inv1;
            o2[0] = oC[mt][nt][2] * inv2; o2[1] = oC[mt][nt][3] * inv2;
        }
    }
}

// ---------------------------------------------------------------------------
extern "C" void kernel_launch(void* const* d_in, const int* in_sizes, int n_in,
                              void* d_out, int out_size)
{
    const float* q  = (const float*)d_in[0];
    const float* k  = (const float*)d_in[1];
    const float* v  = (const float*)d_in[2];
    const float* ub = (const float*)d_in[3];
    const float* vb = (const float*)d_in[4];
    const float* R  = (const float*)d_in[5];
    float* out = (float*)d_out;

    cudaFuncSetAttribute(pos_mma, cudaFuncAttributeMaxDynamicSharedMemorySize, POS_SMEM);
    cudaFuncSetAttribute(flash_mma, cudaFuncAttributeMaxDynamicSharedMemorySize, FLASH_SMEM);

    pos_mma<<<dim3(8, 8, 64), 256, POS_SMEM>>>(q, vb, R);
    flash_mma<<<dim3(8, 64), 256, FLASH_SMEM>>>(q, k, v, ub, out);
}

// round 6
// speedup vs baseline: 1.9158x; 1.9158x over previous
#include <cuda_runtime.h>
#include <cuda_bf16.h>
#include <cstdint>

#define PITCH 1026
// g_pos[n][i][t + s(i)], s(i)=(i+1)&1 -> flash shifted reads are 8B aligned
__device__ float g_pos[(size_t)64 * 1024 * PITCH];

// ------------------------------ helpers -----------------------------------
__device__ __forceinline__ uint32_t smem_u32(const void* p) {
    uint32_t a;
    asm("{ .reg .u64 t; cvta.to.shared.u64 t, %1; cvt.u32.u64 %0, t; }" : "=r"(a) : "l"(p));
    return a;
}
__device__ __forceinline__ void ldsm4(uint32_t* r, uint32_t a) {
    asm volatile("ldmatrix.sync.aligned.m8n8.x4.shared.b16 {%0,%1,%2,%3}, [%4];"
        : "=r"(r[0]), "=r"(r[1]), "=r"(r[2]), "=r"(r[3]) : "r"(a));
}
__device__ __forceinline__ void ldsm2(uint32_t* r, uint32_t a) {
    asm volatile("ldmatrix.sync.aligned.m8n8.x2.shared.b16 {%0,%1}, [%2];"
        : "=r"(r[0]), "=r"(r[1]) : "r"(a));
}
__device__ __forceinline__ void mma16816(float* c, const uint32_t* a, const uint32_t* b) {
    asm volatile("mma.sync.aligned.m16n8k16.row.col.f32.bf16.bf16.f32 "
        "{%0,%1,%2,%3}, {%4,%5,%6,%7}, {%8,%9}, {%0,%1,%2,%3};"
        : "+f"(c[0]), "+f"(c[1]), "+f"(c[2]), "+f"(c[3])
        : "r"(a[0]), "r"(a[1]), "r"(a[2]), "r"(a[3]), "r"(b[0]), "r"(b[1]));
}
__device__ __forceinline__ void splitpair(float a, float b, uint32_t& hi, uint32_t& lo) {
    __nv_bfloat16 ah = __float2bfloat16_rn(a), bh = __float2bfloat16_rn(b);
    __nv_bfloat16 al = __float2bfloat16_rn(a - __bfloat162float(ah));
    __nv_bfloat16 bl = __float2bfloat16_rn(b - __bfloat162float(bh));
    __nv_bfloat162 h2, l2; h2.x = ah; h2.y = bh; l2.x = al; l2.y = bl;
    hi = *reinterpret_cast<uint32_t*>(&h2); lo = *reinterpret_cast<uint32_t*>(&l2);
}
__device__ __forceinline__ float posval(const float* pb, int i, int j) {
    if (j <= i)     return pb[(size_t)i * PITCH + (1023 + j - i + ((i + 1) & 1))];
    if (j == i + 1) return 0.0f;
    return pb[(size_t)(i + 1) * PITCH + (j - i - 2 + ((i + 2) & 1))];
}
__device__ __forceinline__ float2 pos2(const float* pb, int i, int j) {
    if (j + 1 <= i)
        return *(const float2*)(pb + (size_t)i * PITCH + (1023 - i + ((i + 1) & 1)) + j);
    if (j >= i + 2)
        return *(const float2*)(pb + (size_t)(i + 1) * PITCH + (((i + 2) & 1) - i - 2) + j);
    float2 r;
    r.x = posval(pb, i, j);
    r.y = posval(pb, i, j + 1);
    return r;
}

// ---------------------------------------------------------------------------
// Kernel 1: g_pos(shifted) = (q*0.125 + vbias) . R^T  via mma.sync bf16x3.
// Tile 128(i) x 64(t). grid (16 t, 8 i, 64 n), 256 thr = 8 warps 2(M)x4(N).
// smem 55296 -> 4 CTAs/SM.
// ---------------------------------------------------------------------------
#define PQH 0
#define PQL 18432
#define PRH 36864
#define PRL 46080
#define POS_SMEM 55296

__global__ __launch_bounds__(256)
void pos_mma(const float* __restrict__ q, const float* __restrict__ vbias,
             const float* __restrict__ R)
{
    extern __shared__ char cb[];
    uint32_t sb = smem_u32(cb);

    const int tid = threadIdx.x, lane = tid & 31, wid = tid >> 5;
    const int wm = wid >> 2, wn = wid & 3;
    const int n = blockIdx.z, h = n & 15;
    const int i0 = blockIdx.y << 7, t0 = blockIdx.x << 6;

    const float* qb = q + (size_t)n * 65536 + (size_t)i0 * 64;
    const float* rb = R + (size_t)h * (2048 * 64) + (size_t)t0 * 64;

    #pragma unroll
    for (int it = 0; it < 8; ++it) {
        int fi = it * 256 + tid;
        int r = fi >> 4, d = (fi & 15) << 2;
        float4 f = *(const float4*)(qb + r * 64 + d);
        float4 bs = *(const float4*)(vbias + h * 64 + d);
        f.x = f.x * 0.125f + bs.x; f.y = f.y * 0.125f + bs.y;
        f.z = f.z * 0.125f + bs.z; f.w = f.w * 0.125f + bs.w;
        uint2 H, L;
        splitpair(f.x, f.y, H.x, L.x); splitpair(f.z, f.w, H.y, L.y);
        *(uint2*)(cb + PQH + r * 144 + d * 2) = H;
        *(uint2*)(cb + PQL + r * 144 + d * 2) = L;
    }
    #pragma unroll
    for (int it = 0; it < 4; ++it) {
        int fi = it * 256 + tid;
        int r = fi >> 4, d = (fi & 15) << 2;
        float4 g = *(const float4*)(rb + r * 64 + d);
        uint2 H, L;
        splitpair(g.x, g.y, H.x, L.x); splitpair(g.z, g.w, H.y, L.y);
        *(uint2*)(cb + PRH + r * 144 + d * 2) = H;
        *(uint2*)(cb + PRL + r * 144 + d * 2) = L;
    }
    __syncthreads();

    float C[4][2][4] = {};

    #pragma unroll
    for (int ks = 0; ks < 4; ++ks) {
        uint32_t a[4][4], bh[2][2], bl[2][2];
        #pragma unroll
        for (int mt = 0; mt < 4; ++mt)
            ldsm4(a[mt], sb + PQH + (wm * 64 + mt * 16 + (lane & 15)) * 144 +
                         (ks * 16 + ((lane >> 4) << 3)) * 2);
        #pragma unroll
        for (int nt = 0; nt < 2; ++nt) {
            uint32_t ao = (wn * 16 + nt * 8 + (lane & 7)) * 144 +
                          (ks * 16 + (((lane >> 3) & 1) << 3)) * 2;
            ldsm2(bh[nt], sb + PRH + ao);
            ldsm2(bl[nt], sb + PRL + ao);
        }
        #pragma unroll
        for (int mt = 0; mt < 4; ++mt)
            #pragma unroll
            for (int nt = 0; nt < 2; ++nt) {
                mma16816(C[mt][nt], a[mt], bh[nt]);
                mma16816(C[mt][nt], a[mt], bl[nt]);
            }
    }
    #pragma unroll
    for (int ks = 0; ks < 4; ++ks) {
        uint32_t a[4][4], bh[2][2];
        #pragma unroll
        for (int mt = 0; mt < 4; ++mt)
            ldsm4(a[mt], sb + PQL + (wm * 64 + mt * 16 + (lane & 15)) * 144 +
                         (ks * 16 + ((lane >> 4) << 3)) * 2);
        #pragma unroll
        for (int nt = 0; nt < 2; ++nt)
            ldsm2(bh[nt], sb + PRH + (wn * 16 + nt * 8 + (lane & 7)) * 144 +
                          (ks * 16 + (((lane >> 3) & 1) << 3)) * 2);
        #pragma unroll
        for (int mt = 0; mt < 4; ++mt)
            #pragma unroll
            for (int nt = 0; nt < 2; ++nt)
                mma16816(C[mt][nt], a[mt], bh[nt]);
    }

    float* gpn = g_pos + (size_t)n * (1024 * PITCH);
    #pragma unroll
    for (int mt = 0; mt < 4; ++mt) {
        const int i1 = i0 + wm * 64 + mt * 16 + (lane >> 2);
        const int i2 = i1 + 8;
        float* r1 = gpn + (size_t)i1 * PITCH + ((i1 + 1) & 1);
        float* r2 = gpn + (size_t)i2 * PITCH + ((i2 + 1) & 1);
        #pragma unroll
        for (int nt = 0; nt < 2; ++nt) {
            const int jc = t0 + wn * 16 + nt * 8 + ((lane & 3) << 1);
            r1[jc] = C[mt][nt][0]; r1[jc + 1] = C[mt][nt][1];
            r2[jc] = C[mt][nt][2]; r2[jc + 1] = C[mt][nt][3];
        }
    }
}

// ---------------------------------------------------------------------------
// Kernel 2: flash attention via mma.sync bf16x3. BM=128(i), BN=64(j), 16 iters.
// smem 112640 -> 2 CTAs/SM. Pos gathers prefetched into regs before S-MMA.
// grid (8 i-tiles, 64 n), 256 thr = 8 warps 2(M)x4(N).
// ---------------------------------------------------------------------------
#define QUH_O 0
#define QUL_O 18432
#define KH_O  36864
#define KL_O  46080
#define VTH_O 55296
#define VTL_O 64512
#define PH_O  73728
#define PL_O  92160
#define LS_O  110592
#define FLASH_SMEM (LS_O + 2048)

__global__ __launch_bounds__(256)
void flash_mma(const float* __restrict__ q, const float* __restrict__ k,
               const float* __restrict__ v, const float* __restrict__ ubias,
               float* __restrict__ out)
{
    extern __shared__ char cb[];
    uint32_t sb = smem_u32(cb);

    const int tid = threadIdx.x, lane = tid & 31, wid = tid >> 5;
    const int wm = wid >> 2, wn = wid & 3;
    const int n = blockIdx.y, h = n & 15;
    const int i0 = blockIdx.x << 7;

    // stage Qu = q*0.125 + u_bias (hi/lo)
    const float* qb = q + (size_t)n * 65536 + (size_t)i0 * 64;
    #pragma unroll
    for (int it = 0; it < 8; ++it) {
        int fi = it * 256 + tid;
        int r = fi >> 4, d = (fi & 15) << 2;
        float4 f = *(const float4*)(qb + r * 64 + d);
        float4 bs = *(const float4*)(ubias + h * 64 + d);
        f.x = f.x * 0.125f + bs.x; f.y = f.y * 0.125f + bs.y;
        f.z = f.z * 0.125f + bs.z; f.w = f.w * 0.125f + bs.w;
        uint2 H, L;
        splitpair(f.x, f.y, H.x, L.x); splitpair(f.z, f.w, H.y, L.y);
        *(uint2*)(cb + QUH_O + r * 144 + d * 2) = H;
        *(uint2*)(cb + QUL_O + r * 144 + d * 2) = L;
    }

    float oC[4][2][4] = {};
    float ls[8] = {};
    const float* pb  = g_pos + (size_t)n * (1024 * PITCH);
    const float* kb0 = k + (size_t)n * 65536;
    const float* vb0 = v + (size_t)n * 65536;

    for (int kt = 0; kt < 16; ++kt) {
        __syncthreads();   // prev PV done reading P/Vt/K before restage

        // ---- stage K (hi/lo, [j][72]bf16) and V^T (hi/lo, [d][72]bf16) ----
        const float* kb = kb0 + ((size_t)kt << 12);
        const float* vb = vb0 + ((size_t)kt << 12);
        #pragma unroll
        for (int it = 0; it < 4; ++it) {
            int fi = it * 256 + tid;
            int r = fi >> 4, d = (fi & 15) << 2;
            float4 f = *(const float4*)(kb + r * 64 + d);
            uint2 H, L;
            splitpair(f.x, f.y, H.x, L.x); splitpair(f.z, f.w, H.y, L.y);
            *(uint2*)(cb + KH_O + r * 144 + d * 2) = H;
            *(uint2*)(cb + KL_O + r * 144 + d * 2) = L;
            float4 g = *(const float4*)(vb + r * 64 + d);
            float gv[4] = {g.x, g.y, g.z, g.w};
            #pragma unroll
            for (int rr = 0; rr < 4; ++rr) {
                int dd = d + rr;
                __nv_bfloat16 hh = __float2bfloat16_rn(gv[rr]);
                __nv_bfloat16 ll = __float2bfloat16_rn(gv[rr] - __bfloat162float(hh));
                *(__nv_bfloat16*)(cb + VTH_O + dd * 144 + r * 2) = hh;
                *(__nv_bfloat16*)(cb + VTL_O + dd * 144 + r * 2) = ll;
            }
        }

        // ---- prefetch shifted pos values (independent of S-MMA) ----
        float pr[4][2][4];
        #pragma unroll
        for (int mt = 0; mt < 4; ++mt) {
            const int ir1 = wm * 64 + mt * 16 + (lane >> 2);
            const int i1 = i0 + ir1, i2 = i1 + 8;
            #pragma unroll
            for (int nt = 0; nt < 2; ++nt) {
                const int j = (kt << 6) + wn * 16 + nt * 8 + ((lane & 3) << 1);
                float2 pp = pos2(pb, i1, j);
                pr[mt][nt][0] = pp.x; pr[mt][nt][1] = pp.y;
                pp = pos2(pb, i2, j);
                pr[mt][nt][2] = pp.x; pr[mt][nt][3] = pp.y;
            }
        }
        __syncthreads();

        // ---- S = Qu . K^T  (bf16x3) ----
        float sC[4][2][4] = {};
        #pragma unroll
        for (int ks = 0; ks < 4; ++ks) {
            uint32_t a[4][4], bh[2][2], bl[2][2];
            #pragma unroll
            for (int mt = 0; mt < 4; ++mt)
                ldsm4(a[mt], sb + QUH_O + (wm * 64 + mt * 16 + (lane & 15)) * 144 +
                             (ks * 16 + ((lane >> 4) << 3)) * 2);
            #pragma unroll
            for (int nt = 0; nt < 2; ++nt) {
                uint32_t ao = (wn * 16 + nt * 8 + (lane & 7)) * 144 +
                              (ks * 16 + (((lane >> 3) & 1) << 3)) * 2;
                ldsm2(bh[nt], sb + KH_O + ao);
                ldsm2(bl[nt], sb + KL_O + ao);
            }
            #pragma unroll
            for (int mt = 0; mt < 4; ++mt)
                #pragma unroll
                for (int nt = 0; nt < 2; ++nt) {
                    mma16816(sC[mt][nt], a[mt], bh[nt]);
                    mma16816(sC[mt][nt], a[mt], bl[nt]);
                }
        }
        #pragma unroll
        for (int ks = 0; ks < 4; ++ks) {
            uint32_t a[4][4], bh[2][2];
            #pragma unroll
            for (int mt = 0; mt < 4; ++mt)
                ldsm4(a[mt], sb + QUL_O + (wm * 64 + mt * 16 + (lane & 15)) * 144 +
                             (ks * 16 + ((lane >> 4) << 3)) * 2);
            #pragma unroll
            for (int nt = 0; nt < 2; ++nt)
                ldsm2(bh[nt], sb + KH_O + (wn * 16 + nt * 8 + (lane & 7)) * 144 +
                              (ks * 16 + (((lane >> 3) & 1) << 3)) * 2);
            #pragma unroll
            for (int mt = 0; mt < 4; ++mt)
                #pragma unroll
                for (int nt = 0; nt < 2; ++nt)
                    mma16816(sC[mt][nt], a[mt], bh[nt]);
        }

        // ---- add prefetched pos, exp (no max-sub), split -> P smem ----
        #pragma unroll
        for (int mt = 0; mt < 4; ++mt) {
            const int ir1 = wm * 64 + mt * 16 + (lane >> 2);
            #pragma unroll
            for (int nt = 0; nt < 2; ++nt) {
                const int jloc = wn * 16 + nt * 8 + ((lane & 3) << 1);
                float e0 = __expf(sC[mt][nt][0] + pr[mt][nt][0]);
                float e1 = __expf(sC[mt][nt][1] + pr[mt][nt][1]);
                ls[mt * 2] += e0 + e1;
                uint32_t H, L;
                splitpair(e0, e1, H, L);
                *(uint32_t*)(cb + PH_O + ir1 * 144 + jloc * 2) = H;
                *(uint32_t*)(cb + PL_O + ir1 * 144 + jloc * 2) = L;
                e0 = __expf(sC[mt][nt][2] + pr[mt][nt][2]);
                e1 = __expf(sC[mt][nt][3] + pr[mt][nt][3]);
                ls[mt * 2 + 1] += e0 + e1;
                splitpair(e0, e1, H, L);
                *(uint32_t*)(cb + PH_O + (ir1 + 8) * 144 + jloc * 2) = H;
                *(uint32_t*)(cb + PL_O + (ir1 + 8) * 144 + jloc * 2) = L;
            }
        }
        __syncthreads();

        // ---- O += P . V  (bf16x3, fp32 reg accum), K-dim = 64 ----
        #pragma unroll
        for (int ks = 0; ks < 4; ++ks) {
            uint32_t aH[4][4], bH[2][2], bL[2][2];
            #pragma unroll
            for (int mt = 0; mt < 4; ++mt)
                ldsm4(aH[mt], sb + PH_O + (wm * 64 + mt * 16 + (lane & 15)) * 144 +
                              (ks * 16 + ((lane >> 4) << 3)) * 2);
            #pragma unroll
            for (int nt = 0; nt < 2; ++nt) {
                uint32_t ao = (wn * 16 + nt * 8 + (lane & 7)) * 144 +
                              (ks * 16 + (((lane >> 3) & 1) << 3)) * 2;
                ldsm2(bH[nt], sb + VTH_O + ao);
                ldsm2(bL[nt], sb + VTL_O + ao);
            }
            #pragma unroll
            for (int mt = 0; mt < 4; ++mt)
                #pragma unroll
                for (int nt = 0; nt < 2; ++nt) {
                    mma16816(oC[mt][nt], aH[mt], bH[nt]);
                    mma16816(oC[mt][nt], aH[mt], bL[nt]);
                }
        }
        #pragma unroll
        for (int ks = 0; ks < 4; ++ks) {
            uint32_t aL[4][4], bH[2][2];
            #pragma unroll
            for (int mt = 0; mt < 4; ++mt)
                ldsm4(aL[mt], sb + PL_O + (wm * 64 + mt * 16 + (lane & 15)) * 144 +
                              (ks * 16 + ((lane >> 4) << 3)) * 2);
            #pragma unroll
            for (int nt = 0; nt < 2; ++nt)
                ldsm2(bH[nt], sb + VTH_O + (wn * 16 + nt * 8 + (lane & 7)) * 144 +
                              (ks * 16 + (((lane >> 3) & 1) << 3)) * 2);
            #pragma unroll
            for (int mt = 0; mt < 4; ++mt)
                #pragma unroll
                for (int nt = 0; nt < 2; ++nt)
                    mma16816(oC[mt][nt], aL[mt], bH[nt]);
        }
    }

    // ---- row-sum reduction across quad + 4 N-warps ----
    float* lsm = (float*)(cb + LS_O);
    #pragma unroll
    for (int p = 0; p < 8; ++p) {
        float vv = ls[p];
        vv += __shfl_xor_sync(0xffffffffu, vv, 1);
        vv += __shfl_xor_sync(0xffffffffu, vv, 2);
        ls[p] = vv;
    }
    if ((lane & 3) == 0) {
        #pragma unroll
        for (int mt = 0; mt < 4; ++mt) {
            int ir1 = wm * 64 + mt * 16 + (lane >> 2);
            lsm[wn * 128 + ir1] = ls[mt * 2];
            lsm[wn * 128 + ir1 + 8] = ls[mt * 2 + 1];
        }
    }
    __syncthreads();

    // ---- normalize + store O ----
    #pragma unroll
    for (int mt = 0; mt < 4; ++mt) {
        const int ir1 = wm * 64 + mt * 16 + (lane >> 2);
        const int ir2 = ir1 + 8;
        float inv1 = 1.0f / (lsm[ir1] + lsm[128 + ir1] + lsm[256 + ir1] + lsm[384 + ir1]);
        float inv2 = 1.0f / (lsm[ir2] + lsm[128 + ir2] + lsm[256 + ir2] + lsm[384 + ir2]);
        #pragma unroll
        for (int nt = 0; nt < 2; ++nt) {
            const int dcol = wn * 16 + nt * 8 + ((lane & 3) << 1);
            float* o1 = out + (size_t)n * 65536 + (size_t)(i0 + ir1) * 64 + dcol;
            float* o2 = out + (size_t)n * 65536 + (size_t)(i0 + ir2) * 64 + dcol;
            o1[0] = oC[mt][nt][0] * inv1; o1[1] = oC[mt][nt][1] * inv1;
            o2[0] = oC[mt][nt][2] * inv2; o2[1] = oC[mt][nt][3] * inv2;
        }
    }
}

// ---------------------------------------------------------------------------
extern "C" void kernel_launch(void* const* d_in, const int* in_sizes, int n_in,
                              void* d_out, int out_size)
{
    const float* q  = (const float*)d_in[0];
    const float* k  = (const float*)d_in[1];
    const float* v  = (const float*)d_in[2];
    const float* ub = (const float*)d_in[3];
    const float* vb = (const float*)d_in[4];
    const float* R  = (const float*)d_in[5];
    float* out = (float*)d_out;

    cudaFuncSetAttribute(pos_mma, cudaFuncAttributeMaxDynamicSharedMemorySize, POS_SMEM);
    cudaFuncSetAttribute(flash_mma, cudaFuncAttributeMaxDynamicSharedMemorySize, FLASH_SMEM);

    pos_mma<<<dim3(16, 8, 64), 256, POS_SMEM>>>(q, vb, R);
    flash_mma<<<dim3(8, 64), 256, FLASH_SMEM>>>(q, k, v, ub, out);
}